// round 10
// baseline (speedup 1.0000x reference)
#include <cuda_runtime.h>
#include <cstdint>

// SimpleZoneODE — GCN layers are dead code. Effective computation per row r:
//   c1 = bd1 + person@Wd1[32:40] + timeMLP(t)@Wd1[40:56]            [64]
//   h1 = relu(ze[r]@Wd1[0:32] + c1); h2 = relu(h1@Wd2+bd2); out = h2@Wd3+bd3
// R5 design (resubmit #5 after infra timeouts): single fused kernel (c1
// computed per-block, overlapped with cp.async weight staging). 64-thread
// blocks, launch_bounds(64,11) -> 22 warps/SM and a single wave (1563 blocks
// vs 1628 slots). Register diet: layer1 in 2 column-halves x 4 k-chunks
// (z streamed 8 floats at a time). Packed fma.rn.f32x2; LDS.128 weight reads.

typedef unsigned long long ull;

static __device__ __forceinline__ ull fma2(ull a, ull b, ull c) {
    ull d;
    asm("fma.rn.f32x2 %0, %1, %2, %3;" : "=l"(d) : "l"(a), "l"(b), "l"(c));
    return d;
}
static __device__ __forceinline__ ull pack2(float x, float y) {
    ull r;
    asm("mov.b64 %0, {%1, %2};" : "=l"(r) : "f"(x), "f"(y));
    return r;
}
static __device__ __forceinline__ float2 unpack2(ull v) {
    float2 r;
    asm("mov.b64 {%0, %1}, %2;" : "=f"(r.x), "=f"(r.y) : "l"(v));
    return r;
}
static __device__ __forceinline__ void cp16(uint32_t smem, const void* g) {
    asm volatile("cp.async.cg.shared.global [%0], [%1], 16;" :: "r"(smem), "l"(g));
}

__global__ __launch_bounds__(64, 11) void zone_fused_kernel(
    const float* __restrict__ ze,     // [n,32]
    const float* __restrict__ t,      // [1]
    const float* __restrict__ person, // [8]
    const float* __restrict__ Wt1,    // [1,16]
    const float* __restrict__ bt1,    // [16]
    const float* __restrict__ Wt2,    // [16,16]
    const float* __restrict__ bt2,    // [16]
    const float* __restrict__ Wd1,    // [56,64]
    const float* __restrict__ bd1,    // [64]
    const float* __restrict__ Wd2,    // [64,32]
    const float* __restrict__ bd2,    // [32]
    const float* __restrict__ Wd3,    // [32,32]
    const float* __restrict__ bd3,    // [32]
    float* __restrict__ out,          // [n,32]
    int n)
{
    __shared__ __align__(16) ull sW1[32 * 32];   // Wd1 rows 0..31, [k][colpair]
    __shared__ __align__(16) ull sW2[64 * 16];   // Wd2 [k][colpair]
    __shared__ __align__(16) ull sW3[32 * 16];   // Wd3 [k][colpair]
    __shared__ __align__(16) ull sB2[16];
    __shared__ __align__(16) ull sB3[16];
    __shared__ __align__(16) float sC1f[64];

    const int tid = threadIdx.x;  // 0..63

    // ---- Stage all weights via cp.async (overlapped with c1 compute) ----
    {
        const uint32_t a1 = (uint32_t)__cvta_generic_to_shared(sW1);
        const uint32_t a2 = (uint32_t)__cvta_generic_to_shared(sW2);
        const uint32_t a3 = (uint32_t)__cvta_generic_to_shared(sW3);
        const char* g1 = (const char*)Wd1;   // first 8192 B = rows 0..31
        const char* g2 = (const char*)Wd2;
        const char* g3 = (const char*)Wd3;
#pragma unroll
        for (int i = 0; i < 8; i++) {
            const int off = (tid + 64 * i) * 16;
            cp16(a1 + off, g1 + off);
            cp16(a2 + off, g2 + off);
        }
#pragma unroll
        for (int i = 0; i < 4; i++) {
            const int off = (tid + 64 * i) * 16;
            cp16(a3 + off, g3 + off);
        }
        if (tid < 8)
            cp16((uint32_t)__cvta_generic_to_shared(sB2) + tid * 16,
                 (const char*)bd2 + tid * 16);
        else if (tid < 16)
            cp16((uint32_t)__cvta_generic_to_shared(sB3) + (tid - 8) * 16,
                 (const char*)bd3 + (tid - 8) * 16);
        asm volatile("cp.async.commit_group;" ::: "memory");
    }

    // ---- c1[tid]: row-invariant part of layer 1 (redundant per block) ----
    {
        const float tt = t[0];
        float hid[16];
#pragma unroll
        for (int i = 0; i < 16; i++)
            hid[i] = fmaxf(fmaf(tt, Wt1[i], bt1[i]), 0.f);

        float s = bd1[tid];
#pragma unroll
        for (int ii = 0; ii < 16; ii++) {
            float tv = bt2[ii];
#pragma unroll
            for (int i = 0; i < 16; i++)
                tv = fmaf(hid[i], Wt2[i * 16 + ii], tv);
            s = fmaf(tv, Wd1[(40 + ii) * 64 + tid], s);
        }
#pragma unroll
        for (int p = 0; p < 8; p++)
            s = fmaf(person[p], Wd1[(32 + p) * 64 + tid], s);
        sC1f[tid] = s;
    }

    asm volatile("cp.async.wait_group 0;" ::: "memory");
    __syncthreads();

    const ull* sC1 = (const ull*)sC1f;

    const int r = blockIdx.x * 64 + tid;
    const bool v = (r < n);
    const float4* zrow = (const float4*)(ze + (size_t)r * 32);

    // h2 accumulators (layer-2 pre-activation), init bd2.
    ull h2[16];
#pragma unroll
    for (int jp = 0; jp < 16; jp++) h2[jp] = sB2[jp];

    // ---- Layer 1 (+fold into layer 2), two 32-col halves ----
#pragma unroll
    for (int half = 0; half < 2; half++) {
        ull acc[16];
#pragma unroll
        for (int jq = 0; jq < 16; jq++) acc[jq] = sC1[half * 16 + jq];

        // k in 4 chunks of 8 (z streamed; 2nd-half re-reads are L1 hits)
#pragma unroll
        for (int c = 0; c < 4; c++) {
            float4 z0 = make_float4(0.f, 0.f, 0.f, 0.f), z1 = z0;
            if (v) { z0 = zrow[2 * c]; z1 = zrow[2 * c + 1]; }
            float zc[8] = {z0.x, z0.y, z0.z, z0.w, z1.x, z1.y, z1.z, z1.w};
#pragma unroll
            for (int k = 0; k < 8; k++) {
                const int kg = c * 8 + k;
                const ull s = pack2(zc[k], zc[k]);
                const ulonglong2* wrow =
                    (const ulonglong2*)(sW1 + kg * 32 + half * 16);
#pragma unroll
                for (int q = 0; q < 8; q++) {
                    const ulonglong2 w = wrow[q];
                    acc[2 * q]     = fma2(s, w.x, acc[2 * q]);
                    acc[2 * q + 1] = fma2(s, w.y, acc[2 * q + 1]);
                }
            }
        }

        // relu(acc) @ Wd2[half*32 .. half*32+31, :] -> h2
#pragma unroll
        for (int kp = 0; kp < 16; kp++) {
            const float2 p = unpack2(acc[kp]);
            const float a0 = fmaxf(p.x, 0.f), a1 = fmaxf(p.y, 0.f);
            const ull s0 = pack2(a0, a0), s1 = pack2(a1, a1);
            const int kg = half * 32 + 2 * kp;
            const ulonglong2* w0r = (const ulonglong2*)(sW2 + kg * 16);
            const ulonglong2* w1r = (const ulonglong2*)(sW2 + (kg + 1) * 16);
#pragma unroll
            for (int q = 0; q < 8; q++) {
                const ulonglong2 w0 = w0r[q];
                const ulonglong2 w1 = w1r[q];
                h2[2 * q]     = fma2(s0, w0.x, h2[2 * q]);
                h2[2 * q + 1] = fma2(s0, w0.y, h2[2 * q + 1]);
                h2[2 * q]     = fma2(s1, w1.x, h2[2 * q]);
                h2[2 * q + 1] = fma2(s1, w1.y, h2[2 * q + 1]);
            }
        }
    }

    // ---- Layer 3: o = relu(h2) @ Wd3 + bd3 ----
    ull o[16];
#pragma unroll
    for (int jp = 0; jp < 16; jp++) o[jp] = sB3[jp];
#pragma unroll
    for (int kp = 0; kp < 16; kp++) {
        const float2 p = unpack2(h2[kp]);
        const float a0 = fmaxf(p.x, 0.f), a1 = fmaxf(p.y, 0.f);
        const ull s0 = pack2(a0, a0), s1 = pack2(a1, a1);
        const ulonglong2* w0r = (const ulonglong2*)(sW3 + (2 * kp) * 16);
        const ulonglong2* w1r = (const ulonglong2*)(sW3 + (2 * kp + 1) * 16);
#pragma unroll
        for (int q = 0; q < 8; q++) {
            const ulonglong2 w0 = w0r[q];
            const ulonglong2 w1 = w1r[q];
            o[2 * q]     = fma2(s0, w0.x, o[2 * q]);
            o[2 * q + 1] = fma2(s0, w0.y, o[2 * q + 1]);
            o[2 * q]     = fma2(s1, w1.x, o[2 * q]);
            o[2 * q + 1] = fma2(s1, w1.y, o[2 * q + 1]);
        }
    }

    if (v) {
        ulonglong2* p = (ulonglong2*)(out + (size_t)r * 32);
#pragma unroll
        for (int q = 0; q < 8; q++)
            p[q] = make_ulonglong2(o[2 * q], o[2 * q + 1]);
    }
}

// ---------------------------------------------------------------------------
// Inputs: 0 t, 1 zone_embedding, 2 zone_features, 3 person_attrs,
// 4 edge_index, 5 W1, 6 b1, 7 W2, 8 b2, 9 Wt1, 10 bt1, 11 Wt2, 12 bt2,
// 13 Wd1, 14 bd1, 15 Wd2, 16 bd2, 17 Wd3, 18 bd3.  Output [n,32] f32.
// ---------------------------------------------------------------------------
extern "C" void kernel_launch(void* const* d_in, const int* in_sizes, int n_in,
                              void* d_out, int out_size)
{
    const float* t      = (const float*)d_in[0];
    const float* ze     = (const float*)d_in[1];
    const float* person = (const float*)d_in[3];
    const float* Wt1    = (const float*)d_in[9];
    const float* bt1    = (const float*)d_in[10];
    const float* Wt2    = (const float*)d_in[11];
    const float* bt2    = (const float*)d_in[12];
    const float* Wd1    = (const float*)d_in[13];
    const float* bd1    = (const float*)d_in[14];
    const float* Wd2    = (const float*)d_in[15];
    const float* bd2    = (const float*)d_in[16];
    const float* Wd3    = (const float*)d_in[17];
    const float* bd3    = (const float*)d_in[18];
    float* out = (float*)d_out;

    const int n = in_sizes[1] / 32;
    const int blocks = (n + 63) / 64;

    zone_fused_kernel<<<blocks, 64>>>(ze, t, person, Wt1, bt1, Wt2, bt2,
                                      Wd1, bd1, Wd2, bd2, Wd3, bd3, out, n);
}

// round 11
// speedup vs baseline: 1.1325x; 1.1325x over previous
#include <cuda_runtime.h>
#include <cstdint>

// SimpleZoneODE — GCN layers are dead code. Effective computation per row r:
//   c1 = bd1 + person@Wd1[32:40] + timeMLP(t)@Wd1[40:56]            [64]
//   h1 = relu(ze[r]@Wd1[0:32] + c1); h2 = relu(h1@Wd2+bd2); out = h2@Wd3+bd3
// R6: fused kernel with PARALLEL prologue (threads 0-63 compute c1, threads
// 64-127 stage weights via cp.async) and 128 rows/block to amortize it.
// launch_bounds(128,6) -> 24 warps/SM, single wave (782 blocks vs 888 slots).
// Mainloop identical to R5 (regs ~80): packed fma.rn.f32x2, LDS.128 weights.

typedef unsigned long long ull;

static __device__ __forceinline__ ull fma2(ull a, ull b, ull c) {
    ull d;
    asm("fma.rn.f32x2 %0, %1, %2, %3;" : "=l"(d) : "l"(a), "l"(b), "l"(c));
    return d;
}
static __device__ __forceinline__ ull pack2(float x, float y) {
    ull r;
    asm("mov.b64 %0, {%1, %2};" : "=l"(r) : "f"(x), "f"(y));
    return r;
}
static __device__ __forceinline__ float2 unpack2(ull v) {
    float2 r;
    asm("mov.b64 {%0, %1}, %2;" : "=f"(r.x), "=f"(r.y) : "l"(v));
    return r;
}
static __device__ __forceinline__ void cp16(uint32_t smem, const void* g) {
    asm volatile("cp.async.cg.shared.global [%0], [%1], 16;" :: "r"(smem), "l"(g));
}

__global__ __launch_bounds__(128, 6) void zone_fused_kernel(
    const float* __restrict__ ze,     // [n,32]
    const float* __restrict__ t,      // [1]
    const float* __restrict__ person, // [8]
    const float* __restrict__ Wt1,    // [1,16]
    const float* __restrict__ bt1,    // [16]
    const float* __restrict__ Wt2,    // [16,16]
    const float* __restrict__ bt2,    // [16]
    const float* __restrict__ Wd1,    // [56,64]
    const float* __restrict__ bd1,    // [64]
    const float* __restrict__ Wd2,    // [64,32]
    const float* __restrict__ bd2,    // [32]
    const float* __restrict__ Wd3,    // [32,32]
    const float* __restrict__ bd3,    // [32]
    float* __restrict__ out,          // [n,32]
    int n)
{
    __shared__ __align__(16) ull sW1[32 * 32];   // Wd1 rows 0..31, [k][colpair]
    __shared__ __align__(16) ull sW2[64 * 16];   // Wd2 [k][colpair]
    __shared__ __align__(16) ull sW3[32 * 16];   // Wd3 [k][colpair]
    __shared__ __align__(16) ull sB2[16];
    __shared__ __align__(16) ull sB3[16];
    __shared__ __align__(16) float sC1f[64];

    const int tid = threadIdx.x;  // 0..127

    // ---- Parallel prologue ----
    if (tid >= 64) {
        // Threads 64..127: stage all weights via cp.async.
        const int s = tid - 64;  // 0..63
        const uint32_t a1 = (uint32_t)__cvta_generic_to_shared(sW1);
        const uint32_t a2 = (uint32_t)__cvta_generic_to_shared(sW2);
        const uint32_t a3 = (uint32_t)__cvta_generic_to_shared(sW3);
        const char* g1 = (const char*)Wd1;   // first 8192 B = rows 0..31
        const char* g2 = (const char*)Wd2;
        const char* g3 = (const char*)Wd3;
#pragma unroll
        for (int i = 0; i < 8; i++) {
            const int off = (s + 64 * i) * 16;
            cp16(a1 + off, g1 + off);
            cp16(a2 + off, g2 + off);
        }
#pragma unroll
        for (int i = 0; i < 4; i++) {
            const int off = (s + 64 * i) * 16;
            cp16(a3 + off, g3 + off);
        }
        if (s < 8)
            cp16((uint32_t)__cvta_generic_to_shared(sB2) + s * 16,
                 (const char*)bd2 + s * 16);
        else if (s < 16)
            cp16((uint32_t)__cvta_generic_to_shared(sB3) + (s - 8) * 16,
                 (const char*)bd3 + (s - 8) * 16);
        asm volatile("cp.async.commit_group;" ::: "memory");
        asm volatile("cp.async.wait_group 0;" ::: "memory");
    } else {
        // Threads 0..63: c1[tid] = row-invariant part of layer 1.
        const float tt = t[0];
        float hid[16];
#pragma unroll
        for (int i = 0; i < 16; i++)
            hid[i] = fmaxf(fmaf(tt, Wt1[i], bt1[i]), 0.f);

        float s = bd1[tid];
#pragma unroll
        for (int ii = 0; ii < 16; ii++) {
            float tv = bt2[ii];
#pragma unroll
            for (int i = 0; i < 16; i++)
                tv = fmaf(hid[i], Wt2[i * 16 + ii], tv);
            s = fmaf(tv, Wd1[(40 + ii) * 64 + tid], s);
        }
#pragma unroll
        for (int p = 0; p < 8; p++)
            s = fmaf(person[p], Wd1[(32 + p) * 64 + tid], s);
        sC1f[tid] = s;
    }
    __syncthreads();

    const ull* sC1 = (const ull*)sC1f;

    const int r = blockIdx.x * 128 + tid;
    const bool v = (r < n);
    const float4* zrow = (const float4*)(ze + (size_t)r * 32);

    // h2 accumulators (layer-2 pre-activation), init bd2.
    ull h2[16];
#pragma unroll
    for (int jp = 0; jp < 16; jp++) h2[jp] = sB2[jp];

    // ---- Layer 1 (+fold into layer 2), two 32-col halves ----
#pragma unroll
    for (int half = 0; half < 2; half++) {
        ull acc[16];
#pragma unroll
        for (int jq = 0; jq < 16; jq++) acc[jq] = sC1[half * 16 + jq];

        // k in 4 chunks of 8 (z streamed; 2nd-half re-reads are L1 hits)
#pragma unroll
        for (int c = 0; c < 4; c++) {
            float4 z0 = make_float4(0.f, 0.f, 0.f, 0.f), z1 = z0;
            if (v) { z0 = zrow[2 * c]; z1 = zrow[2 * c + 1]; }
            float zc[8] = {z0.x, z0.y, z0.z, z0.w, z1.x, z1.y, z1.z, z1.w};
#pragma unroll
            for (int k = 0; k < 8; k++) {
                const int kg = c * 8 + k;
                const ull s = pack2(zc[k], zc[k]);
                const ulonglong2* wrow =
                    (const ulonglong2*)(sW1 + kg * 32 + half * 16);
#pragma unroll
                for (int q = 0; q < 8; q++) {
                    const ulonglong2 w = wrow[q];
                    acc[2 * q]     = fma2(s, w.x, acc[2 * q]);
                    acc[2 * q + 1] = fma2(s, w.y, acc[2 * q + 1]);
                }
            }
        }

        // relu(acc) @ Wd2[half*32 .. half*32+31, :] -> h2
#pragma unroll
        for (int kp = 0; kp < 16; kp++) {
            const float2 p = unpack2(acc[kp]);
            const float a0 = fmaxf(p.x, 0.f), a1 = fmaxf(p.y, 0.f);
            const ull s0 = pack2(a0, a0), s1 = pack2(a1, a1);
            const int kg = half * 32 + 2 * kp;
            const ulonglong2* w0r = (const ulonglong2*)(sW2 + kg * 16);
            const ulonglong2* w1r = (const ulonglong2*)(sW2 + (kg + 1) * 16);
#pragma unroll
            for (int q = 0; q < 8; q++) {
                const ulonglong2 w0 = w0r[q];
                const ulonglong2 w1 = w1r[q];
                h2[2 * q]     = fma2(s0, w0.x, h2[2 * q]);
                h2[2 * q + 1] = fma2(s0, w0.y, h2[2 * q + 1]);
                h2[2 * q]     = fma2(s1, w1.x, h2[2 * q]);
                h2[2 * q + 1] = fma2(s1, w1.y, h2[2 * q + 1]);
            }
        }
    }

    // ---- Layer 3: o = relu(h2) @ Wd3 + bd3 ----
    ull o[16];
#pragma unroll
    for (int jp = 0; jp < 16; jp++) o[jp] = sB3[jp];
#pragma unroll
    for (int kp = 0; kp < 16; kp++) {
        const float2 p = unpack2(h2[kp]);
        const float a0 = fmaxf(p.x, 0.f), a1 = fmaxf(p.y, 0.f);
        const ull s0 = pack2(a0, a0), s1 = pack2(a1, a1);
        const ulonglong2* w0r = (const ulonglong2*)(sW3 + (2 * kp) * 16);
        const ulonglong2* w1r = (const ulonglong2*)(sW3 + (2 * kp + 1) * 16);
#pragma unroll
        for (int q = 0; q < 8; q++) {
            const ulonglong2 w0 = w0r[q];
            const ulonglong2 w1 = w1r[q];
            o[2 * q]     = fma2(s0, w0.x, o[2 * q]);
            o[2 * q + 1] = fma2(s0, w0.y, o[2 * q + 1]);
            o[2 * q]     = fma2(s1, w1.x, o[2 * q]);
            o[2 * q + 1] = fma2(s1, w1.y, o[2 * q + 1]);
        }
    }

    if (v) {
        ulonglong2* p = (ulonglong2*)(out + (size_t)r * 32);
#pragma unroll
        for (int q = 0; q < 8; q++)
            p[q] = make_ulonglong2(o[2 * q], o[2 * q + 1]);
    }
}

// ---------------------------------------------------------------------------
// Inputs: 0 t, 1 zone_embedding, 2 zone_features, 3 person_attrs,
// 4 edge_index, 5 W1, 6 b1, 7 W2, 8 b2, 9 Wt1, 10 bt1, 11 Wt2, 12 bt2,
// 13 Wd1, 14 bd1, 15 Wd2, 16 bd2, 17 Wd3, 18 bd3.  Output [n,32] f32.
// ---------------------------------------------------------------------------
extern "C" void kernel_launch(void* const* d_in, const int* in_sizes, int n_in,
                              void* d_out, int out_size)
{
    const float* t      = (const float*)d_in[0];
    const float* ze     = (const float*)d_in[1];
    const float* person = (const float*)d_in[3];
    const float* Wt1    = (const float*)d_in[9];
    const float* bt1    = (const float*)d_in[10];
    const float* Wt2    = (const float*)d_in[11];
    const float* bt2    = (const float*)d_in[12];
    const float* Wd1    = (const float*)d_in[13];
    const float* bd1    = (const float*)d_in[14];
    const float* Wd2    = (const float*)d_in[15];
    const float* bd2    = (const float*)d_in[16];
    const float* Wd3    = (const float*)d_in[17];
    const float* bd3    = (const float*)d_in[18];
    float* out = (float*)d_out;

    const int n = in_sizes[1] / 32;
    const int blocks = (n + 127) / 128;

    zone_fused_kernel<<<blocks, 128>>>(ze, t, person, Wt1, bt1, Wt2, bt2,
                                       Wd1, bd1, Wd2, bd2, Wd3, bd3, out, n);
}

// round 13
// speedup vs baseline: 1.4021x; 1.2380x over previous
#include <cuda_runtime.h>
#include <cstdint>

// SimpleZoneODE — GCN layers are dead code. Effective computation per row r:
//   c1 = bd1 + person@Wd1[32:40] + timeMLP(t)@Wd1[40:56]            [64]
//   h1 = relu(ze[r]@Wd1[0:32] + c1); h2 = relu(h1@Wd2+bd2); out = h2@Wd3+bd3
// R7 (resubmit after infra timeout): the kernel is smem-return-BW bound
// (L1~74% across R4/R6; broadcast LDS.128 delivers 512B for 16B of unique
// weights). Fix: 2 rows/thread so each weight LDS.128 feeds 4 FFMA2
// (2 cols x 2 rows) — LDS/row drops 1280->512. Register control: layer1 in
// quarters (acc 8 ull x 2 rows), fold-into-h2 per quarter; layer3 in halves;
// z streamed 4 floats/row. 128 thr/block, 256 rows/block,
// launch_bounds(128,4); parallel prologue (c1 on threads 0-63, cp.async
// weight staging on threads 64-127).

typedef unsigned long long ull;

static __device__ __forceinline__ ull fma2(ull a, ull b, ull c) {
    ull d;
    asm("fma.rn.f32x2 %0, %1, %2, %3;" : "=l"(d) : "l"(a), "l"(b), "l"(c));
    return d;
}
static __device__ __forceinline__ ull pack2(float x, float y) {
    ull r;
    asm("mov.b64 %0, {%1, %2};" : "=l"(r) : "f"(x), "f"(y));
    return r;
}
static __device__ __forceinline__ float2 unpack2(ull v) {
    float2 r;
    asm("mov.b64 {%0, %1}, %2;" : "=f"(r.x), "=f"(r.y) : "l"(v));
    return r;
}
static __device__ __forceinline__ void cp16(uint32_t smem, const void* g) {
    asm volatile("cp.async.cg.shared.global [%0], [%1], 16;" :: "r"(smem), "l"(g));
}

__global__ __launch_bounds__(128, 4) void zone_fused2_kernel(
    const float* __restrict__ ze,     // [n,32]
    const float* __restrict__ t,      // [1]
    const float* __restrict__ person, // [8]
    const float* __restrict__ Wt1,    // [1,16]
    const float* __restrict__ bt1,    // [16]
    const float* __restrict__ Wt2,    // [16,16]
    const float* __restrict__ bt2,    // [16]
    const float* __restrict__ Wd1,    // [56,64]
    const float* __restrict__ bd1,    // [64]
    const float* __restrict__ Wd2,    // [64,32]
    const float* __restrict__ bd2,    // [32]
    const float* __restrict__ Wd3,    // [32,32]
    const float* __restrict__ bd3,    // [32]
    float* __restrict__ out,          // [n,32]
    int n)
{
    __shared__ __align__(16) ull sW1[32 * 32];   // Wd1 rows 0..31, [k][colpair]
    __shared__ __align__(16) ull sW2[64 * 16];   // Wd2 [k][colpair]
    __shared__ __align__(16) ull sW3[32 * 16];   // Wd3 [k][colpair]
    __shared__ __align__(16) ull sB2[16];
    __shared__ __align__(16) ull sB3[16];
    __shared__ __align__(16) float sC1f[64];

    const int tid = threadIdx.x;  // 0..127

    // ---- Parallel prologue ----
    if (tid >= 64) {
        // Threads 64..127: stage all weights via cp.async.
        const int s = tid - 64;  // 0..63
        const uint32_t a1 = (uint32_t)__cvta_generic_to_shared(sW1);
        const uint32_t a2 = (uint32_t)__cvta_generic_to_shared(sW2);
        const uint32_t a3 = (uint32_t)__cvta_generic_to_shared(sW3);
        const char* g1 = (const char*)Wd1;   // first 8192 B = rows 0..31
        const char* g2 = (const char*)Wd2;
        const char* g3 = (const char*)Wd3;
#pragma unroll
        for (int i = 0; i < 8; i++) {
            const int off = (s + 64 * i) * 16;
            cp16(a1 + off, g1 + off);
            cp16(a2 + off, g2 + off);
        }
#pragma unroll
        for (int i = 0; i < 4; i++) {
            const int off = (s + 64 * i) * 16;
            cp16(a3 + off, g3 + off);
        }
        if (s < 8)
            cp16((uint32_t)__cvta_generic_to_shared(sB2) + s * 16,
                 (const char*)bd2 + s * 16);
        else if (s < 16)
            cp16((uint32_t)__cvta_generic_to_shared(sB3) + (s - 8) * 16,
                 (const char*)bd3 + (s - 8) * 16);
        asm volatile("cp.async.commit_group;" ::: "memory");
        asm volatile("cp.async.wait_group 0;" ::: "memory");
    } else {
        // Threads 0..63: c1[tid] = row-invariant part of layer 1.
        const float tt = t[0];
        float hid[16];
#pragma unroll
        for (int i = 0; i < 16; i++)
            hid[i] = fmaxf(fmaf(tt, Wt1[i], bt1[i]), 0.f);

        float s = bd1[tid];
#pragma unroll
        for (int ii = 0; ii < 16; ii++) {
            float tv = bt2[ii];
#pragma unroll
            for (int i = 0; i < 16; i++)
                tv = fmaf(hid[i], Wt2[i * 16 + ii], tv);
            s = fmaf(tv, Wd1[(40 + ii) * 64 + tid], s);
        }
#pragma unroll
        for (int p = 0; p < 8; p++)
            s = fmaf(person[p], Wd1[(32 + p) * 64 + tid], s);
        sC1f[tid] = s;
    }
    __syncthreads();

    const ull* sC1 = (const ull*)sC1f;

    const int r0 = blockIdx.x * 256 + tid;   // row A
    const int r1 = r0 + 128;                 // row B
    const bool vA = (r0 < n);
    const bool vB = (r1 < n);
    const float4* zA4 = (const float4*)(ze + (size_t)r0 * 32);
    const float4* zB4 = (const float4*)(ze + (size_t)r1 * 32);

    // h2 accumulators (layer-2 pre-activation) for both rows, init bd2.
    ull h2A[16], h2B[16];
#pragma unroll
    for (int jp = 0; jp < 16; jp++) { h2A[jp] = sB2[jp]; h2B[jp] = h2A[jp]; }

    // ---- Layer 1 in four 16-col quarters, each folded into layer 2 ----
#pragma unroll
    for (int q4 = 0; q4 < 4; q4++) {
        ull accA[8], accB[8];
#pragma unroll
        for (int j = 0; j < 8; j++) { accA[j] = sC1[q4 * 8 + j]; accB[j] = accA[j]; }

        // k in 8 chunks of 4 (z streamed 4 floats/row; re-reads hit L1)
#pragma unroll
        for (int c = 0; c < 8; c++) {
            float4 a = make_float4(0.f, 0.f, 0.f, 0.f), b = a;
            if (vA) a = zA4[c];
            if (vB) b = zB4[c];
            const float za[4] = {a.x, a.y, a.z, a.w};
            const float zb[4] = {b.x, b.y, b.z, b.w};
#pragma unroll
            for (int k = 0; k < 4; k++) {
                const int kg = c * 4 + k;
                const ull sA = pack2(za[k], za[k]);
                const ull sB = pack2(zb[k], zb[k]);
                const ulonglong2* wr =
                    (const ulonglong2*)(sW1 + kg * 32 + q4 * 8);
#pragma unroll
                for (int q = 0; q < 4; q++) {
                    const ulonglong2 w = wr[q];
                    accA[2 * q]     = fma2(sA, w.x, accA[2 * q]);
                    accA[2 * q + 1] = fma2(sA, w.y, accA[2 * q + 1]);
                    accB[2 * q]     = fma2(sB, w.x, accB[2 * q]);
                    accB[2 * q + 1] = fma2(sB, w.y, accB[2 * q + 1]);
                }
            }
        }

        // Fold: relu(h1 quarter) @ Wd2[q4*16 .. q4*16+15, :] -> h2
#pragma unroll
        for (int kp = 0; kp < 8; kp++) {
            const float2 pA = unpack2(accA[kp]);
            const float2 pB = unpack2(accB[kp]);
            const ull sA0 = pack2(fmaxf(pA.x, 0.f), fmaxf(pA.x, 0.f));
            const ull sA1 = pack2(fmaxf(pA.y, 0.f), fmaxf(pA.y, 0.f));
            const ull sB0 = pack2(fmaxf(pB.x, 0.f), fmaxf(pB.x, 0.f));
            const ull sB1 = pack2(fmaxf(pB.y, 0.f), fmaxf(pB.y, 0.f));
            const int kg = q4 * 16 + 2 * kp;
            const ulonglong2* w0r = (const ulonglong2*)(sW2 + kg * 16);
            const ulonglong2* w1r = (const ulonglong2*)(sW2 + (kg + 1) * 16);
#pragma unroll
            for (int q = 0; q < 8; q++) {
                const ulonglong2 w0 = w0r[q];
                const ulonglong2 w1 = w1r[q];
                h2A[2 * q]     = fma2(sA0, w0.x, h2A[2 * q]);
                h2A[2 * q + 1] = fma2(sA0, w0.y, h2A[2 * q + 1]);
                h2A[2 * q]     = fma2(sA1, w1.x, h2A[2 * q]);
                h2A[2 * q + 1] = fma2(sA1, w1.y, h2A[2 * q + 1]);
                h2B[2 * q]     = fma2(sB0, w0.x, h2B[2 * q]);
                h2B[2 * q + 1] = fma2(sB0, w0.y, h2B[2 * q + 1]);
                h2B[2 * q]     = fma2(sB1, w1.x, h2B[2 * q]);
                h2B[2 * q + 1] = fma2(sB1, w1.y, h2B[2 * q + 1]);
            }
        }
    }

    // relu(h2) in place
#pragma unroll
    for (int kp = 0; kp < 16; kp++) {
        const float2 pA = unpack2(h2A[kp]);
        const float2 pB = unpack2(h2B[kp]);
        h2A[kp] = pack2(fmaxf(pA.x, 0.f), fmaxf(pA.y, 0.f));
        h2B[kp] = pack2(fmaxf(pB.x, 0.f), fmaxf(pB.y, 0.f));
    }

    // ---- Layer 3 in two 16-col halves: o = relu(h2) @ Wd3 + bd3 ----
#pragma unroll
    for (int h = 0; h < 2; h++) {
        ull oA[8], oB[8];
#pragma unroll
        for (int j = 0; j < 8; j++) { oA[j] = sB3[h * 8 + j]; oB[j] = oA[j]; }

#pragma unroll
        for (int kp = 0; kp < 16; kp++) {
            const float2 pA = unpack2(h2A[kp]);
            const float2 pB = unpack2(h2B[kp]);
            const ull sA0 = pack2(pA.x, pA.x);
            const ull sA1 = pack2(pA.y, pA.y);
            const ull sB0 = pack2(pB.x, pB.x);
            const ull sB1 = pack2(pB.y, pB.y);
            const ulonglong2* w0r =
                (const ulonglong2*)(sW3 + (2 * kp) * 16 + h * 8);
            const ulonglong2* w1r =
                (const ulonglong2*)(sW3 + (2 * kp + 1) * 16 + h * 8);
#pragma unroll
            for (int q = 0; q < 4; q++) {
                const ulonglong2 w0 = w0r[q];
                const ulonglong2 w1 = w1r[q];
                oA[2 * q]     = fma2(sA0, w0.x, oA[2 * q]);
                oA[2 * q + 1] = fma2(sA0, w0.y, oA[2 * q + 1]);
                oA[2 * q]     = fma2(sA1, w1.x, oA[2 * q]);
                oA[2 * q + 1] = fma2(sA1, w1.y, oA[2 * q + 1]);
                oB[2 * q]     = fma2(sB0, w0.x, oB[2 * q]);
                oB[2 * q + 1] = fma2(sB0, w0.y, oB[2 * q + 1]);
                oB[2 * q]     = fma2(sB1, w1.x, oB[2 * q]);
                oB[2 * q + 1] = fma2(sB1, w1.y, oB[2 * q + 1]);
            }
        }

        if (vA) {
            ulonglong2* p = (ulonglong2*)(out + (size_t)r0 * 32 + h * 16);
#pragma unroll
            for (int q = 0; q < 4; q++)
                p[q] = make_ulonglong2(oA[2 * q], oA[2 * q + 1]);
        }
        if (vB) {
            ulonglong2* p = (ulonglong2*)(out + (size_t)r1 * 32 + h * 16);
#pragma unroll
            for (int q = 0; q < 4; q++)
                p[q] = make_ulonglong2(oB[2 * q], oB[2 * q + 1]);
        }
    }
}

// ---------------------------------------------------------------------------
// Inputs: 0 t, 1 zone_embedding, 2 zone_features, 3 person_attrs,
// 4 edge_index, 5 W1, 6 b1, 7 W2, 8 b2, 9 Wt1, 10 bt1, 11 Wt2, 12 bt2,
// 13 Wd1, 14 bd1, 15 Wd2, 16 bd2, 17 Wd3, 18 bd3.  Output [n,32] f32.
// ---------------------------------------------------------------------------
extern "C" void kernel_launch(void* const* d_in, const int* in_sizes, int n_in,
                              void* d_out, int out_size)
{
    const float* t      = (const float*)d_in[0];
    const float* ze     = (const float*)d_in[1];
    const float* person = (const float*)d_in[3];
    const float* Wt1    = (const float*)d_in[9];
    const float* bt1    = (const float*)d_in[10];
    const float* Wt2    = (const float*)d_in[11];
    const float* bt2    = (const float*)d_in[12];
    const float* Wd1    = (const float*)d_in[13];
    const float* bd1    = (const float*)d_in[14];
    const float* Wd2    = (const float*)d_in[15];
    const float* bd2    = (const float*)d_in[16];
    const float* Wd3    = (const float*)d_in[17];
    const float* bd3    = (const float*)d_in[18];
    float* out = (float*)d_out;

    const int n = in_sizes[1] / 32;
    const int blocks = (n + 255) / 256;

    zone_fused2_kernel<<<blocks, 128>>>(ze, t, person, Wt1, bt1, Wt2, bt2,
                                        Wd1, bd1, Wd2, bd2, Wd3, bd3, out, n);
}

// round 15
// speedup vs baseline: 1.5536x; 1.1080x over previous
#include <cuda_runtime.h>
#include <cstdint>

// SimpleZoneODE — GCN layers are dead code. Effective computation per row r:
//   c1 = bd1 + person@Wd1[32:40] + timeMLP(t)@Wd1[40:56]            [64]
//   h1 = relu(ze[r]@Wd1[0:32] + c1); h2 = relu(h1@Wd2+bd2); out = h2@Wd3+bd3
// R8 (resubmit after infra timeout): R7 showed 2-rows/thread fixed the
// LDS-BW bottleneck (L1 74->58%) but is latency-bound at 10.5 warps/SM
// (grid-limited). Registers are free up to ~170 (only 3 blocks/SM needed).
// Spend them on ILP: layer-1 in 32-col HALVES (acc 16 ull x 2 rows) ->
// 2x longer independent FMA runs + deeper LDS batching. launch_bounds(128,3).
// Else as R7: parallel prologue, 2 rows/thr, 256 rows/block, fma.rn.f32x2.

typedef unsigned long long ull;

static __device__ __forceinline__ ull fma2(ull a, ull b, ull c) {
    ull d;
    asm("fma.rn.f32x2 %0, %1, %2, %3;" : "=l"(d) : "l"(a), "l"(b), "l"(c));
    return d;
}
static __device__ __forceinline__ ull pack2(float x, float y) {
    ull r;
    asm("mov.b64 %0, {%1, %2};" : "=l"(r) : "f"(x), "f"(y));
    return r;
}
static __device__ __forceinline__ float2 unpack2(ull v) {
    float2 r;
    asm("mov.b64 {%0, %1}, %2;" : "=f"(r.x), "=f"(r.y) : "l"(v));
    return r;
}
static __device__ __forceinline__ void cp16(uint32_t smem, const void* g) {
    asm volatile("cp.async.cg.shared.global [%0], [%1], 16;" :: "r"(smem), "l"(g));
}

__global__ __launch_bounds__(128, 3) void zone_fused3_kernel(
    const float* __restrict__ ze,     // [n,32]
    const float* __restrict__ t,      // [1]
    const float* __restrict__ person, // [8]
    const float* __restrict__ Wt1,    // [1,16]
    const float* __restrict__ bt1,    // [16]
    const float* __restrict__ Wt2,    // [16,16]
    const float* __restrict__ bt2,    // [16]
    const float* __restrict__ Wd1,    // [56,64]
    const float* __restrict__ bd1,    // [64]
    const float* __restrict__ Wd2,    // [64,32]
    const float* __restrict__ bd2,    // [32]
    const float* __restrict__ Wd3,    // [32,32]
    const float* __restrict__ bd3,    // [32]
    float* __restrict__ out,          // [n,32]
    int n)
{
    __shared__ __align__(16) ull sW1[32 * 32];   // Wd1 rows 0..31, [k][colpair]
    __shared__ __align__(16) ull sW2[64 * 16];   // Wd2 [k][colpair]
    __shared__ __align__(16) ull sW3[32 * 16];   // Wd3 [k][colpair]
    __shared__ __align__(16) ull sB2[16];
    __shared__ __align__(16) ull sB3[16];
    __shared__ __align__(16) float sC1f[64];

    const int tid = threadIdx.x;  // 0..127

    // ---- Parallel prologue ----
    if (tid >= 64) {
        // Threads 64..127: stage all weights via cp.async.
        const int s = tid - 64;  // 0..63
        const uint32_t a1 = (uint32_t)__cvta_generic_to_shared(sW1);
        const uint32_t a2 = (uint32_t)__cvta_generic_to_shared(sW2);
        const uint32_t a3 = (uint32_t)__cvta_generic_to_shared(sW3);
        const char* g1 = (const char*)Wd1;   // first 8192 B = rows 0..31
        const char* g2 = (const char*)Wd2;
        const char* g3 = (const char*)Wd3;
#pragma unroll
        for (int i = 0; i < 8; i++) {
            const int off = (s + 64 * i) * 16;
            cp16(a1 + off, g1 + off);
            cp16(a2 + off, g2 + off);
        }
#pragma unroll
        for (int i = 0; i < 4; i++) {
            const int off = (s + 64 * i) * 16;
            cp16(a3 + off, g3 + off);
        }
        if (s < 8)
            cp16((uint32_t)__cvta_generic_to_shared(sB2) + s * 16,
                 (const char*)bd2 + s * 16);
        else if (s < 16)
            cp16((uint32_t)__cvta_generic_to_shared(sB3) + (s - 8) * 16,
                 (const char*)bd3 + (s - 8) * 16);
        asm volatile("cp.async.commit_group;" ::: "memory");
        asm volatile("cp.async.wait_group 0;" ::: "memory");
    } else {
        // Threads 0..63: c1[tid] = row-invariant part of layer 1.
        const float tt = t[0];
        float hid[16];
#pragma unroll
        for (int i = 0; i < 16; i++)
            hid[i] = fmaxf(fmaf(tt, Wt1[i], bt1[i]), 0.f);

        float s = bd1[tid];
#pragma unroll
        for (int ii = 0; ii < 16; ii++) {
            float tv = bt2[ii];
#pragma unroll
            for (int i = 0; i < 16; i++)
                tv = fmaf(hid[i], Wt2[i * 16 + ii], tv);
            s = fmaf(tv, Wd1[(40 + ii) * 64 + tid], s);
        }
#pragma unroll
        for (int p = 0; p < 8; p++)
            s = fmaf(person[p], Wd1[(32 + p) * 64 + tid], s);
        sC1f[tid] = s;
    }
    __syncthreads();

    const ull* sC1 = (const ull*)sC1f;

    const int r0 = blockIdx.x * 256 + tid;   // row A
    const int r1 = r0 + 128;                 // row B
    const bool vA = (r0 < n);
    const bool vB = (r1 < n);
    const float4* zA4 = (const float4*)(ze + (size_t)r0 * 32);
    const float4* zB4 = (const float4*)(ze + (size_t)r1 * 32);

    // h2 accumulators (layer-2 pre-activation) for both rows, init bd2.
    ull h2A[16], h2B[16];
#pragma unroll
    for (int jp = 0; jp < 16; jp++) { h2A[jp] = sB2[jp]; h2B[jp] = h2A[jp]; }

    // ---- Layer 1 in two 32-col halves, each folded into layer 2 ----
#pragma unroll
    for (int half = 0; half < 2; half++) {
        ull accA[16], accB[16];
#pragma unroll
        for (int j = 0; j < 16; j++) { accA[j] = sC1[half * 16 + j]; accB[j] = accA[j]; }

        // k in 8 chunks of 4 (z streamed 4 floats/row; 2nd-half re-reads hit L1)
#pragma unroll
        for (int c = 0; c < 8; c++) {
            float4 a = make_float4(0.f, 0.f, 0.f, 0.f), b = a;
            if (vA) a = zA4[c];
            if (vB) b = zB4[c];
            const float za[4] = {a.x, a.y, a.z, a.w};
            const float zb[4] = {b.x, b.y, b.z, b.w};
#pragma unroll
            for (int k = 0; k < 4; k++) {
                const int kg = c * 4 + k;
                const ull sA = pack2(za[k], za[k]);
                const ull sB = pack2(zb[k], zb[k]);
                const ulonglong2* wr =
                    (const ulonglong2*)(sW1 + kg * 32 + half * 16);
#pragma unroll
                for (int q = 0; q < 8; q++) {
                    const ulonglong2 w = wr[q];
                    accA[2 * q]     = fma2(sA, w.x, accA[2 * q]);
                    accA[2 * q + 1] = fma2(sA, w.y, accA[2 * q + 1]);
                    accB[2 * q]     = fma2(sB, w.x, accB[2 * q]);
                    accB[2 * q + 1] = fma2(sB, w.y, accB[2 * q + 1]);
                }
            }
        }

        // Fold: relu(h1 half) @ Wd2[half*32 .. half*32+31, :] -> h2
#pragma unroll
        for (int kp = 0; kp < 16; kp++) {
            const float2 pA = unpack2(accA[kp]);
            const float2 pB = unpack2(accB[kp]);
            const ull sA0 = pack2(fmaxf(pA.x, 0.f), fmaxf(pA.x, 0.f));
            const ull sA1 = pack2(fmaxf(pA.y, 0.f), fmaxf(pA.y, 0.f));
            const ull sB0 = pack2(fmaxf(pB.x, 0.f), fmaxf(pB.x, 0.f));
            const ull sB1 = pack2(fmaxf(pB.y, 0.f), fmaxf(pB.y, 0.f));
            const int kg = half * 32 + 2 * kp;
            const ulonglong2* w0r = (const ulonglong2*)(sW2 + kg * 16);
            const ulonglong2* w1r = (const ulonglong2*)(sW2 + (kg + 1) * 16);
#pragma unroll
            for (int q = 0; q < 8; q++) {
                const ulonglong2 w0 = w0r[q];
                const ulonglong2 w1 = w1r[q];
                h2A[2 * q]     = fma2(sA0, w0.x, h2A[2 * q]);
                h2A[2 * q + 1] = fma2(sA0, w0.y, h2A[2 * q + 1]);
                h2A[2 * q]     = fma2(sA1, w1.x, h2A[2 * q]);
                h2A[2 * q + 1] = fma2(sA1, w1.y, h2A[2 * q + 1]);
                h2B[2 * q]     = fma2(sB0, w0.x, h2B[2 * q]);
                h2B[2 * q + 1] = fma2(sB0, w0.y, h2B[2 * q + 1]);
                h2B[2 * q]     = fma2(sB1, w1.x, h2B[2 * q]);
                h2B[2 * q + 1] = fma2(sB1, w1.y, h2B[2 * q + 1]);
            }
        }
    }

    // relu(h2) in place
#pragma unroll
    for (int kp = 0; kp < 16; kp++) {
        const float2 pA = unpack2(h2A[kp]);
        const float2 pB = unpack2(h2B[kp]);
        h2A[kp] = pack2(fmaxf(pA.x, 0.f), fmaxf(pA.y, 0.f));
        h2B[kp] = pack2(fmaxf(pB.x, 0.f), fmaxf(pB.y, 0.f));
    }

    // ---- Layer 3 in two 16-col halves: o = relu(h2) @ Wd3 + bd3 ----
#pragma unroll
    for (int h = 0; h < 2; h++) {
        ull oA[8], oB[8];
#pragma unroll
        for (int j = 0; j < 8; j++) { oA[j] = sB3[h * 8 + j]; oB[j] = oA[j]; }

#pragma unroll
        for (int kp = 0; kp < 16; kp++) {
            const float2 pA = unpack2(h2A[kp]);
            const float2 pB = unpack2(h2B[kp]);
            const ull sA0 = pack2(pA.x, pA.x);
            const ull sA1 = pack2(pA.y, pA.y);
            const ull sB0 = pack2(pB.x, pB.x);
            const ull sB1 = pack2(pB.y, pB.y);
            const ulonglong2* w0r =
                (const ulonglong2*)(sW3 + (2 * kp) * 16 + h * 8);
            const ulonglong2* w1r =
                (const ulonglong2*)(sW3 + (2 * kp + 1) * 16 + h * 8);
#pragma unroll
            for (int q = 0; q < 4; q++) {
                const ulonglong2 w0 = w0r[q];
                const ulonglong2 w1 = w1r[q];
                oA[2 * q]     = fma2(sA0, w0.x, oA[2 * q]);
                oA[2 * q + 1] = fma2(sA0, w0.y, oA[2 * q + 1]);
                oA[2 * q]     = fma2(sA1, w1.x, oA[2 * q]);
                oA[2 * q + 1] = fma2(sA1, w1.y, oA[2 * q + 1]);
                oB[2 * q]     = fma2(sB0, w0.x, oB[2 * q]);
                oB[2 * q + 1] = fma2(sB0, w0.y, oB[2 * q + 1]);
                oB[2 * q]     = fma2(sB1, w1.x, oB[2 * q]);
                oB[2 * q + 1] = fma2(sB1, w1.y, oB[2 * q + 1]);
            }
        }

        if (vA) {
            ulonglong2* p = (ulonglong2*)(out + (size_t)r0 * 32 + h * 16);
#pragma unroll
            for (int q = 0; q < 4; q++)
                p[q] = make_ulonglong2(oA[2 * q], oA[2 * q + 1]);
        }
        if (vB) {
            ulonglong2* p = (ulonglong2*)(out + (size_t)r1 * 32 + h * 16);
#pragma unroll
            for (int q = 0; q < 4; q++)
                p[q] = make_ulonglong2(oB[2 * q], oB[2 * q + 1]);
        }
    }
}

// ---------------------------------------------------------------------------
// Inputs: 0 t, 1 zone_embedding, 2 zone_features, 3 person_attrs,
// 4 edge_index, 5 W1, 6 b1, 7 W2, 8 b2, 9 Wt1, 10 bt1, 11 Wt2, 12 bt2,
// 13 Wd1, 14 bd1, 15 Wd2, 16 bd2, 17 Wd3, 18 bd3.  Output [n,32] f32.
// ---------------------------------------------------------------------------
extern "C" void kernel_launch(void* const* d_in, const int* in_sizes, int n_in,
                              void* d_out, int out_size)
{
    const float* t      = (const float*)d_in[0];
    const float* ze     = (const float*)d_in[1];
    const float* person = (const float*)d_in[3];
    const float* Wt1    = (const float*)d_in[9];
    const float* bt1    = (const float*)d_in[10];
    const float* Wt2    = (const float*)d_in[11];
    const float* bt2    = (const float*)d_in[12];
    const float* Wd1    = (const float*)d_in[13];
    const float* bd1    = (const float*)d_in[14];
    const float* Wd2    = (const float*)d_in[15];
    const float* bd2    = (const float*)d_in[16];
    const float* Wd3    = (const float*)d_in[17];
    const float* bd3    = (const float*)d_in[18];
    float* out = (float*)d_out;

    const int n = in_sizes[1] / 32;
    const int blocks = (n + 255) / 256;

    zone_fused3_kernel<<<blocks, 128>>>(ze, t, person, Wt1, bt1, Wt2, bt2,
                                        Wd1, bd1, Wd2, bd2, Wd3, bd3, out, n);
}